// round 1
// baseline (speedup 1.0000x reference)
#include <cuda_runtime.h>
#include <math.h>

#define BSZ  4
#define TSEQ 2048
#define CDIM 1024

#define BM 64
#define BN 64
#define BK 16

// persistent scratch (no allocs allowed)
__device__ float g_Q[(size_t)BSZ*TSEQ*CDIM];
__device__ float g_K[(size_t)BSZ*TSEQ*CDIM];
__device__ float g_V[(size_t)BSZ*TSEQ*CDIM];
__device__ float g_S[(size_t)BSZ*TSEQ*TSEQ];
__device__ float g_O[(size_t)BSZ*TSEQ*CDIM];

// ---------------------------------------------------------------------------
// NT GEMM: C[m,n] = scale * sum_k A[m,k]*B[n,k] + bias[n]
// optional interleaved-RoPE epilogue (over full N=CDIM), optional causal skip.
// A: M x K row-major, B: N x K row-major.
// ---------------------------------------------------------------------------
template<int ROPE, int CAUSAL>
__global__ void __launch_bounds__(256) gemm_nt_k(
    const float* __restrict__ A, const float* __restrict__ B,
    const float* __restrict__ bias, float* __restrict__ C,
    int M, int N, int K, long sA, long sB, long sC, float scale)
{
    long bz = blockIdx.z;
    A += bz * sA; B += bz * sB; C += bz * sC;
    int m0 = blockIdx.y * BM, n0 = blockIdx.x * BN;
    if (CAUSAL && n0 > m0 + BM - 1) return;   // fully above diagonal

    __shared__ float As[BK][BM + 1];
    __shared__ float Bs[BK][BN + 1];

    int tid = threadIdx.x;
    int tx = tid % 16, ty = tid / 16;
    int lr = tid / 16;       // 0..15
    int lc = tid % 16;       // 0..15

    float acc[4][4] = {};

    for (int k0 = 0; k0 < K; k0 += BK) {
        #pragma unroll
        for (int i = 0; i < 4; i++) {
            int r = lr + 16 * i;
            As[lc][r] = A[(long)(m0 + r) * K + k0 + lc];
            Bs[lc][r] = B[(long)(n0 + r) * K + k0 + lc];
        }
        __syncthreads();
        #pragma unroll
        for (int kk = 0; kk < BK; kk++) {
            float a[4], b[4];
            #pragma unroll
            for (int i = 0; i < 4; i++) a[i] = As[kk][ty * 4 + i];
            #pragma unroll
            for (int j = 0; j < 4; j++) b[j] = Bs[kk][tx * 4 + j];
            #pragma unroll
            for (int i = 0; i < 4; i++)
                #pragma unroll
                for (int j = 0; j < 4; j++)
                    acc[i][j] += a[i] * b[j];
        }
        __syncthreads();
    }

    #pragma unroll
    for (int i = 0; i < 4; i++) {
        int m = m0 + ty * 4 + i;
        #pragma unroll
        for (int j = 0; j < 4; j++) {
            float v = acc[i][j] * scale;
            if (bias) v += bias[n0 + tx * 4 + j];
            acc[i][j] = v;
        }
        if (ROPE) {
            int t = m % TSEQ;
            #pragma unroll
            for (int pp = 0; pp < 2; pp++) {
                int nc = n0 + tx * 4 + 2 * pp;          // even column index
                float ex = (float)nc / (float)CDIM;     // 2p/d
                float freq = powf(10000.0f, -ex);
                float ang = (float)t * freq;
                float s, c;
                sincosf(ang, &s, &c);
                float v0 = acc[i][2 * pp], v1 = acc[i][2 * pp + 1];
                acc[i][2 * pp]     = v0 * c - v1 * s;
                acc[i][2 * pp + 1] = v1 * c + v0 * s;
            }
        }
        #pragma unroll
        for (int j = 0; j < 4; j++)
            C[(long)m * N + n0 + tx * 4 + j] = acc[i][j];
    }
}

// ---------------------------------------------------------------------------
// NN GEMM with causal k-limit: C[m,n] = sum_{k<min(K,m0+BM)} A[m,k]*B[k,n]
// A: M x K row-major (probabilities, zero above causal edge within block),
// B: K x N row-major.
// ---------------------------------------------------------------------------
__global__ void __launch_bounds__(256) gemm_nn_causal_k(
    const float* __restrict__ A, const float* __restrict__ B,
    float* __restrict__ C, int M, int N, int K, long sA, long sB, long sC)
{
    long bz = blockIdx.z;
    A += bz * sA; B += bz * sB; C += bz * sC;
    int m0 = blockIdx.y * BM, n0 = blockIdx.x * BN;
    int kmax = min(K, m0 + BM);   // rows in this block attend to keys < m0+BM

    __shared__ float As[BK][BM + 1];
    __shared__ float Bs[BK][BN + 1];

    int tid = threadIdx.x;
    int tx = tid % 16, ty = tid / 16;
    int lr = tid / 16, lc = tid % 16;
    int bn = tid % 64, bk = tid / 64;   // for B loads

    float acc[4][4] = {};

    for (int k0 = 0; k0 < kmax; k0 += BK) {
        #pragma unroll
        for (int i = 0; i < 4; i++) {
            int r = lr + 16 * i;
            As[lc][r] = A[(long)(m0 + r) * K + k0 + lc];
        }
        #pragma unroll
        for (int i = 0; i < 4; i++) {
            int kr = bk + 4 * i;
            Bs[kr][bn] = B[(long)(k0 + kr) * N + n0 + bn];
        }
        __syncthreads();
        #pragma unroll
        for (int kk = 0; kk < BK; kk++) {
            float a[4], b[4];
            #pragma unroll
            for (int i = 0; i < 4; i++) a[i] = As[kk][ty * 4 + i];
            #pragma unroll
            for (int j = 0; j < 4; j++) b[j] = Bs[kk][tx * 4 + j];
            #pragma unroll
            for (int i = 0; i < 4; i++)
                #pragma unroll
                for (int j = 0; j < 4; j++)
                    acc[i][j] += a[i] * b[j];
        }
        __syncthreads();
    }

    #pragma unroll
    for (int i = 0; i < 4; i++) {
        int m = m0 + ty * 4 + i;
        #pragma unroll
        for (int j = 0; j < 4; j++)
            C[(long)m * N + n0 + tx * 4 + j] = acc[i][j];
    }
}

// ---------------------------------------------------------------------------
// Causal row softmax on S (in place). Row (b,t) has t+1 valid entries.
// Also zeroes entries (t, roundup(t+1,BM)) so the PV k-loop sees zeros.
// ---------------------------------------------------------------------------
__global__ void __launch_bounds__(256) softmax_causal_k(float* __restrict__ S)
{
    long row = blockIdx.x;                    // 0 .. B*T-1
    long b = row / TSEQ;
    int  t = (int)(row % TSEQ);
    float* p = S + b * (long)TSEQ * TSEQ + (long)t * TSEQ;
    int n = t + 1;
    int tid = threadIdx.x;

    float vals[TSEQ / 256];
    float mx = -INFINITY;
    #pragma unroll
    for (int i = 0; i < TSEQ / 256; i++) {
        int idx = tid + 256 * i;
        vals[i] = (idx < n) ? p[idx] : -INFINITY;
        mx = fmaxf(mx, vals[i]);
    }
    __shared__ float red[256];
    red[tid] = mx; __syncthreads();
    for (int s = 128; s > 0; s >>= 1) {
        if (tid < s) red[tid] = fmaxf(red[tid], red[tid + s]);
        __syncthreads();
    }
    mx = red[0]; __syncthreads();

    float sum = 0.f;
    #pragma unroll
    for (int i = 0; i < TSEQ / 256; i++) {
        int idx = tid + 256 * i;
        if (idx < n) { vals[i] = expf(vals[i] - mx); sum += vals[i]; }
        else vals[i] = 0.f;
    }
    red[tid] = sum; __syncthreads();
    for (int s = 128; s > 0; s >>= 1) {
        if (tid < s) red[tid] += red[tid + s];
        __syncthreads();
    }
    float inv = 1.0f / red[0];

    int nz = ((n + BM - 1) / BM) * BM;   // zero through end of this row-block's k range
    #pragma unroll
    for (int i = 0; i < TSEQ / 256; i++) {
        int idx = tid + 256 * i;
        if (idx < n)        p[idx] = vals[i] * inv;
        else if (idx < nz)  p[idx] = 0.f;
    }
}

// ---------------------------------------------------------------------------
extern "C" void kernel_launch(void* const* d_in, const int* in_sizes, int n_in,
                              void* d_out, int out_size)
{
    const float* x  = (const float*)d_in[0];
    const float* Wq = (const float*)d_in[1];
    const float* bq = (const float*)d_in[2];
    const float* Wk = (const float*)d_in[3];
    const float* bk = (const float*)d_in[4];
    const float* Wv = (const float*)d_in[5];
    const float* bv = (const float*)d_in[6];
    const float* Wf = (const float*)d_in[7];
    const float* bf = (const float*)d_in[8];
    float* out = (float*)d_out;

    float *Q, *K, *V, *S, *O;
    cudaGetSymbolAddress((void**)&Q, g_Q);
    cudaGetSymbolAddress((void**)&K, g_K);
    cudaGetSymbolAddress((void**)&V, g_V);
    cudaGetSymbolAddress((void**)&S, g_S);
    cudaGetSymbolAddress((void**)&O, g_O);

    const int M = BSZ * TSEQ;          // 8192
    const int C = CDIM;                // 1024
    const float inv_sqrt_c = 1.0f / 32.0f;

    dim3 blk(256);
    dim3 gProj(C / BN, M / BM, 1);     // 16 x 128

    // Q, K (with RoPE), V projections
    gemm_nt_k<1, 0><<<gProj, blk>>>(x, Wq, bq, Q, M, C, C, 0, 0, 0, 1.0f);
    gemm_nt_k<1, 0><<<gProj, blk>>>(x, Wk, bk, K, M, C, C, 0, 0, 0, 1.0f);
    gemm_nt_k<0, 0><<<gProj, blk>>>(x, Wv, bv, V, M, C, C, 0, 0, 0, 1.0f);

    // S = Q K^T / sqrt(C), batched, causal block skip
    dim3 gS(TSEQ / BN, TSEQ / BM, BSZ);   // 32 x 32 x 4
    gemm_nt_k<0, 1><<<gS, blk>>>(Q, K, nullptr, S,
                                 TSEQ, TSEQ, C,
                                 (long)TSEQ * C, (long)TSEQ * C, (long)TSEQ * TSEQ,
                                 inv_sqrt_c);

    // softmax (causal, in place)
    softmax_causal_k<<<BSZ * TSEQ, blk>>>(S);

    // O = P V, batched, causal k-limit
    dim3 gPV(C / BN, TSEQ / BM, BSZ);     // 16 x 32 x 4
    gemm_nn_causal_k<<<gPV, blk>>>(S, V, O,
                                   TSEQ, C, TSEQ,
                                   (long)TSEQ * TSEQ, (long)TSEQ * C, (long)TSEQ * C);

    // out = O Wf^T + bf
    gemm_nt_k<0, 0><<<gProj, blk>>>(O, Wf, bf, out, M, C, C, 0, 0, 0, 1.0f);
}

// round 2
// speedup vs baseline: 1.4236x; 1.4236x over previous
#include <cuda_runtime.h>
#include <math.h>

#define BSZ  4
#define TSEQ 2048
#define CDIM 1024

// persistent scratch (no allocs allowed)
__device__ float g_Q[(size_t)BSZ*TSEQ*CDIM];
__device__ float g_K[(size_t)BSZ*TSEQ*CDIM];
__device__ float g_V[(size_t)BSZ*TSEQ*CDIM];
__device__ float g_S[(size_t)BSZ*TSEQ*TSEQ];
__device__ float g_O[(size_t)BSZ*TSEQ*CDIM];
__device__ float2 g_CS[(size_t)TSEQ*(CDIM/2)];   // (cos, sin) per (t, pair)

// ---------------------------------------------------------------------------
// RoPE cos/sin table: cs[t][p] for pair p (covers cols 2p, 2p+1)
// ---------------------------------------------------------------------------
__global__ void __launch_bounds__(256) rope_table_k(float2* __restrict__ cs)
{
    int idx = blockIdx.x * 256 + threadIdx.x;     // t*(C/2)+p
    int t = idx / (CDIM / 2);
    int p = idx % (CDIM / 2);
    float freq = powf(10000.0f, -(float)(2 * p) / (float)CDIM);
    float ang = (float)t * freq;
    float s, c;
    sincosf(ang, &s, &c);
    cs[idx] = make_float2(c, s);
}

// 64-FFMA micro-tile on buffer b
#define COMPUTE_TILE(ASM, BSM, b)                                            \
    _Pragma("unroll")                                                        \
    for (int kk = 0; kk < 16; kk++) {                                        \
        float a[8], bb[8];                                                   \
        *(float4*)&a[0]  = *(const float4*)&ASM[b][kk][ty * 8];              \
        *(float4*)&a[4]  = *(const float4*)&ASM[b][kk][ty * 8 + 4];          \
        *(float4*)&bb[0] = *(const float4*)&BSM[b][kk][tx * 8];              \
        *(float4*)&bb[4] = *(const float4*)&BSM[b][kk][tx * 8 + 4];          \
        _Pragma("unroll")                                                    \
        for (int i = 0; i < 8; i++)                                          \
            _Pragma("unroll")                                                \
            for (int j = 0; j < 8; j++)                                      \
                acc[i][j] += a[i] * bb[j];                                   \
    }

// ---------------------------------------------------------------------------
// NT GEMM: C[m,n] = scale*sum_k A[m,k]*B[n,k] + bias[n]  (+ optional RoPE)
// A: M x K row-major, B: N x K row-major. 128x128x16 tile, 8x8/thread.
// ---------------------------------------------------------------------------
template<int ROPE, int CAUSAL>
__global__ void __launch_bounds__(256, 2) gemm_nt(
    const float* __restrict__ A, const float* __restrict__ B,
    const float* __restrict__ bias, const float2* __restrict__ cs,
    float* __restrict__ C, int N, int K,
    long sA, long sB, long sC, float scale)
{
    long bz = blockIdx.z;
    A += bz * sA; B += bz * sB; C += bz * sC;
    int m0 = blockIdx.y * 128, n0 = blockIdx.x * 128;
    if (CAUSAL && n0 > m0 + 127) return;

    __shared__ __align__(16) float As[2][16][128];
    __shared__ __align__(16) float Bs[2][16][128];

    int tid = threadIdx.x;
    int r  = tid & 63;          // 0..63 (loader row)
    int c4 = tid >> 6;          // 0..3  (loader col group, 4 floats)
    int tx = tid & 15, ty = tid >> 4;

    const float* Ap = A + (long)(m0 + r) * K + c4 * 4;
    const float* Bp = B + (long)(n0 + r) * K + c4 * 4;
    const long rowoff = 64L * K;

    float4 pa0, pa1, pb0, pb1;
    float acc[8][8];
    #pragma unroll
    for (int i = 0; i < 8; i++)
        #pragma unroll
        for (int j = 0; j < 8; j++) acc[i][j] = 0.f;

    const int nK = K / 16;

    // prologue: tile 0
    pa0 = *(const float4*)(Ap);
    pa1 = *(const float4*)(Ap + rowoff);
    pb0 = *(const float4*)(Bp);
    pb1 = *(const float4*)(Bp + rowoff);
    {
        int c = c4 * 4;
        As[0][c+0][r] = pa0.x; As[0][c+1][r] = pa0.y; As[0][c+2][r] = pa0.z; As[0][c+3][r] = pa0.w;
        As[0][c+0][r+64] = pa1.x; As[0][c+1][r+64] = pa1.y; As[0][c+2][r+64] = pa1.z; As[0][c+3][r+64] = pa1.w;
        Bs[0][c+0][r] = pb0.x; Bs[0][c+1][r] = pb0.y; Bs[0][c+2][r] = pb0.z; Bs[0][c+3][r] = pb0.w;
        Bs[0][c+0][r+64] = pb1.x; Bs[0][c+1][r+64] = pb1.y; Bs[0][c+2][r+64] = pb1.z; Bs[0][c+3][r+64] = pb1.w;
    }
    __syncthreads();

    int buf = 0;
    for (int kb = 1; kb < nK; kb++) {
        int k0 = kb * 16;
        pa0 = *(const float4*)(Ap + k0);
        pa1 = *(const float4*)(Ap + rowoff + k0);
        pb0 = *(const float4*)(Bp + k0);
        pb1 = *(const float4*)(Bp + rowoff + k0);

        COMPUTE_TILE(As, Bs, buf)

        int nb = buf ^ 1;
        int c = c4 * 4;
        As[nb][c+0][r] = pa0.x; As[nb][c+1][r] = pa0.y; As[nb][c+2][r] = pa0.z; As[nb][c+3][r] = pa0.w;
        As[nb][c+0][r+64] = pa1.x; As[nb][c+1][r+64] = pa1.y; As[nb][c+2][r+64] = pa1.z; As[nb][c+3][r+64] = pa1.w;
        Bs[nb][c+0][r] = pb0.x; Bs[nb][c+1][r] = pb0.y; Bs[nb][c+2][r] = pb0.z; Bs[nb][c+3][r] = pb0.w;
        Bs[nb][c+0][r+64] = pb1.x; Bs[nb][c+1][r+64] = pb1.y; Bs[nb][c+2][r+64] = pb1.z; Bs[nb][c+3][r+64] = pb1.w;
        __syncthreads();
        buf = nb;
    }
    COMPUTE_TILE(As, Bs, buf)

    // epilogue
    float bv[8];
    #pragma unroll
    for (int j = 0; j < 8; j++) bv[j] = bias ? bias[n0 + tx * 8 + j] : 0.f;

    #pragma unroll
    for (int i = 0; i < 8; i++) {
        int m = m0 + ty * 8 + i;
        float v[8];
        #pragma unroll
        for (int j = 0; j < 8; j++) v[j] = acc[i][j] * scale + bv[j];
        if (ROPE) {
            int t = m & (TSEQ - 1);
            const float2* csr = cs + (long)t * (CDIM / 2) + (n0 + tx * 8) / 2;
            #pragma unroll
            for (int p2 = 0; p2 < 4; p2++) {
                float2 sc = csr[p2];
                float v0 = v[2 * p2], v1 = v[2 * p2 + 1];
                v[2 * p2]     = v0 * sc.x - v1 * sc.y;
                v[2 * p2 + 1] = v1 * sc.x + v0 * sc.y;
            }
        }
        float* Cp = C + (long)m * N + n0 + tx * 8;
        *(float4*)Cp       = make_float4(v[0], v[1], v[2], v[3]);
        *(float4*)(Cp + 4) = make_float4(v[4], v[5], v[6], v[7]);
    }
}

// ---------------------------------------------------------------------------
// NN GEMM with causal k-limit: C[m,n] = sum_{k<m0+128} A[m,k]*B[k,n]
// A: M x K row-major (probs), B: K x N row-major.
// ---------------------------------------------------------------------------
__global__ void __launch_bounds__(256, 2) gemm_nn_causal(
    const float* __restrict__ A, const float* __restrict__ B,
    float* __restrict__ C, int N, int K, long sA, long sB, long sC)
{
    long bz = blockIdx.z;
    A += bz * sA; B += bz * sB; C += bz * sC;
    int m0 = blockIdx.y * 128, n0 = blockIdx.x * 128;
    int kmax = min(K, m0 + 128);
    const int nK = kmax / 16;

    __shared__ __align__(16) float As[2][16][128];
    __shared__ __align__(16) float Bs[2][16][128];

    int tid = threadIdx.x;
    int r  = tid & 63;
    int c4 = tid >> 6;
    int bcol = tid & 31;        // *4 cols for B
    int brow = tid >> 5;        // 0..7 (rows brow, brow+8)
    int tx = tid & 15, ty = tid >> 4;

    const float* Ap = A + (long)(m0 + r) * K + c4 * 4;
    const float* Bp = B + (long)brow * N + n0 + bcol * 4;
    const long rowoffA = 64L * K;

    float4 pa0, pa1, pb0, pb1;
    float acc[8][8];
    #pragma unroll
    for (int i = 0; i < 8; i++)
        #pragma unroll
        for (int j = 0; j < 8; j++) acc[i][j] = 0.f;

    // prologue
    pa0 = *(const float4*)(Ap);
    pa1 = *(const float4*)(Ap + rowoffA);
    pb0 = *(const float4*)(Bp);
    pb1 = *(const float4*)(Bp + 8L * N);
    {
        int c = c4 * 4;
        As[0][c+0][r] = pa0.x; As[0][c+1][r] = pa0.y; As[0][c+2][r] = pa0.z; As[0][c+3][r] = pa0.w;
        As[0][c+0][r+64] = pa1.x; As[0][c+1][r+64] = pa1.y; As[0][c+2][r+64] = pa1.z; As[0][c+3][r+64] = pa1.w;
        *(float4*)&Bs[0][brow][bcol * 4]     = pb0;
        *(float4*)&Bs[0][brow + 8][bcol * 4] = pb1;
    }
    __syncthreads();

    int buf = 0;
    for (int kb = 1; kb < nK; kb++) {
        int k0 = kb * 16;
        pa0 = *(const float4*)(Ap + k0);
        pa1 = *(const float4*)(Ap + rowoffA + k0);
        pb0 = *(const float4*)(Bp + (long)k0 * N);
        pb1 = *(const float4*)(Bp + (long)(k0 + 8) * N);

        COMPUTE_TILE(As, Bs, buf)

        int nb = buf ^ 1;
        int c = c4 * 4;
        As[nb][c+0][r] = pa0.x; As[nb][c+1][r] = pa0.y; As[nb][c+2][r] = pa0.z; As[nb][c+3][r] = pa0.w;
        As[nb][c+0][r+64] = pa1.x; As[nb][c+1][r+64] = pa1.y; As[nb][c+2][r+64] = pa1.z; As[nb][c+3][r+64] = pa1.w;
        *(float4*)&Bs[nb][brow][bcol * 4]     = pb0;
        *(float4*)&Bs[nb][brow + 8][bcol * 4] = pb1;
        __syncthreads();
        buf = nb;
    }
    COMPUTE_TILE(As, Bs, buf)

    #pragma unroll
    for (int i = 0; i < 8; i++) {
        int m = m0 + ty * 8 + i;
        float* Cp = C + (long)m * N + n0 + tx * 8;
        *(float4*)Cp       = make_float4(acc[i][0], acc[i][1], acc[i][2], acc[i][3]);
        *(float4*)(Cp + 4) = make_float4(acc[i][4], acc[i][5], acc[i][6], acc[i][7]);
    }
}

// ---------------------------------------------------------------------------
// Causal row softmax on S (in place, full-row write; masked lanes -> 0)
// ---------------------------------------------------------------------------
__global__ void __launch_bounds__(256) softmax_causal_k(float* __restrict__ S)
{
    long row = blockIdx.x;                     // 0 .. B*T-1
    long b = row >> 11;
    int  t = (int)(row & (TSEQ - 1));
    float* p = S + (b << 22) + ((long)t << 11);
    int n = t + 1;
    int tid = threadIdx.x;

    float4 v[2];
    float mx = -INFINITY;
    #pragma unroll
    for (int i = 0; i < 2; i++) {
        int q = tid + 256 * i;
        v[i] = *(const float4*)(p + q * 4);
        float* f = (float*)&v[i];
        int base = q * 4;
        #pragma unroll
        for (int c = 0; c < 4; c++) {
            if (base + c >= n) f[c] = -INFINITY;
            mx = fmaxf(mx, f[c]);
        }
    }

    __shared__ float red[8];
    #pragma unroll
    for (int o = 16; o; o >>= 1) mx = fmaxf(mx, __shfl_xor_sync(~0u, mx, o));
    if ((tid & 31) == 0) red[tid >> 5] = mx;
    __syncthreads();
    mx = red[0];
    #pragma unroll
    for (int k = 1; k < 8; k++) mx = fmaxf(mx, red[k]);
    __syncthreads();

    float sum = 0.f;
    #pragma unroll
    for (int i = 0; i < 2; i++) {
        float* f = (float*)&v[i];
        #pragma unroll
        for (int c = 0; c < 4; c++) {
            float e = expf(f[c] - mx);   // exp(-inf)=0 for masked lanes
            f[c] = e;
            sum += e;
        }
    }
    #pragma unroll
    for (int o = 16; o; o >>= 1) sum += __shfl_xor_sync(~0u, sum, o);
    if ((tid & 31) == 0) red[tid >> 5] = sum;
    __syncthreads();
    sum = 0.f;
    #pragma unroll
    for (int k = 0; k < 8; k++) sum += red[k];
    float inv = 1.0f / sum;

    #pragma unroll
    for (int i = 0; i < 2; i++) {
        int q = tid + 256 * i;
        float* f = (float*)&v[i];
        #pragma unroll
        for (int c = 0; c < 4; c++) f[c] *= inv;
        *(float4*)(p + q * 4) = v[i];
    }
}

// ---------------------------------------------------------------------------
extern "C" void kernel_launch(void* const* d_in, const int* in_sizes, int n_in,
                              void* d_out, int out_size)
{
    const float* x  = (const float*)d_in[0];
    const float* Wq = (const float*)d_in[1];
    const float* bq = (const float*)d_in[2];
    const float* Wk = (const float*)d_in[3];
    const float* bk = (const float*)d_in[4];
    const float* Wv = (const float*)d_in[5];
    const float* bv = (const float*)d_in[6];
    const float* Wf = (const float*)d_in[7];
    const float* bf = (const float*)d_in[8];
    float* out = (float*)d_out;

    float *Q, *K, *V, *S, *O;
    float2* CS;
    cudaGetSymbolAddress((void**)&Q, g_Q);
    cudaGetSymbolAddress((void**)&K, g_K);
    cudaGetSymbolAddress((void**)&V, g_V);
    cudaGetSymbolAddress((void**)&S, g_S);
    cudaGetSymbolAddress((void**)&O, g_O);
    cudaGetSymbolAddress((void**)&CS, g_CS);

    const int M = BSZ * TSEQ;          // 8192
    const int C = CDIM;                // 1024
    const float inv_sqrt_c = 1.0f / 32.0f;

    dim3 blk(256);

    // RoPE table
    rope_table_k<<<TSEQ * (CDIM / 2) / 256, blk>>>(CS);

    dim3 gProj(C / 128, M / 128, 1);   // 8 x 64

    gemm_nt<1, 0><<<gProj, blk>>>(x, Wq, bq, CS, Q, C, C, 0, 0, 0, 1.0f);
    gemm_nt<1, 0><<<gProj, blk>>>(x, Wk, bk, CS, K, C, C, 0, 0, 0, 1.0f);
    gemm_nt<0, 0><<<gProj, blk>>>(x, Wv, bv, nullptr, V, C, C, 0, 0, 0, 1.0f);

    // S = Q K^T / 32, causal block skip
    dim3 gS(TSEQ / 128, TSEQ / 128, BSZ);   // 16 x 16 x 4
    gemm_nt<0, 1><<<gS, blk>>>(Q, K, nullptr, nullptr, S,
                               TSEQ, C,
                               (long)TSEQ * C, (long)TSEQ * C, (long)TSEQ * TSEQ,
                               inv_sqrt_c);

    softmax_causal_k<<<BSZ * TSEQ, blk>>>(S);

    // O = P V, causal k-limit
    dim3 gPV(C / 128, TSEQ / 128, BSZ);     // 8 x 16 x 4
    gemm_nn_causal<<<gPV, blk>>>(S, V, O,
                                 C, TSEQ,
                                 (long)TSEQ * TSEQ, (long)TSEQ * C, (long)TSEQ * C);

    gemm_nt<0, 0><<<gProj, blk>>>(O, Wf, bf, nullptr, out, C, C, 0, 0, 0, 1.0f);
}

// round 5
// speedup vs baseline: 3.0749x; 2.1599x over previous
#include <cuda_runtime.h>
#include <cuda_bf16.h>
#include <math.h>
#include <cstdint>

#define BSZ  4
#define TSEQ 2048
#define CDIM 1024
#define MTOT (BSZ*TSEQ)

typedef __nv_bfloat16 bf16;

#define KC 32
#define LDP 40                       // padded row length (elems) for smem tiles
#define TILE_BYTES (128*LDP*2)       // one buffer, one matrix

// ------------------------- persistent scratch ------------------------------
__device__ __align__(16) bf16 g_Xhi[(size_t)MTOT*CDIM];
__device__ __align__(16) bf16 g_Xlo[(size_t)MTOT*CDIM];
__device__ __align__(16) bf16 g_Wqh[(size_t)CDIM*CDIM];
__device__ __align__(16) bf16 g_Wql[(size_t)CDIM*CDIM];
__device__ __align__(16) bf16 g_Wkh[(size_t)CDIM*CDIM];
__device__ __align__(16) bf16 g_Wkl[(size_t)CDIM*CDIM];
__device__ __align__(16) bf16 g_Wvh[(size_t)CDIM*CDIM];
__device__ __align__(16) bf16 g_Wvl[(size_t)CDIM*CDIM];
__device__ __align__(16) bf16 g_Wfh[(size_t)CDIM*CDIM];
__device__ __align__(16) bf16 g_Wfl[(size_t)CDIM*CDIM];
__device__ __align__(16) bf16 g_Qhi[(size_t)MTOT*CDIM];
__device__ __align__(16) bf16 g_Qlo[(size_t)MTOT*CDIM];
__device__ __align__(16) bf16 g_Khi[(size_t)MTOT*CDIM];
__device__ __align__(16) bf16 g_Klo[(size_t)MTOT*CDIM];
__device__ __align__(16) float g_V  [(size_t)MTOT*CDIM];
__device__ __align__(16) bf16 g_Vth[(size_t)BSZ*CDIM*TSEQ];
__device__ __align__(16) bf16 g_Vtl[(size_t)BSZ*CDIM*TSEQ];
__device__ __align__(16) float g_S  [(size_t)BSZ*TSEQ*TSEQ];
__device__ __align__(16) bf16 g_Phi[(size_t)BSZ*TSEQ*TSEQ];
__device__ __align__(16) bf16 g_Plo[(size_t)BSZ*TSEQ*TSEQ];
__device__ __align__(16) bf16 g_Ohi[(size_t)MTOT*CDIM];
__device__ __align__(16) bf16 g_Olo[(size_t)MTOT*CDIM];
__device__ __align__(16) float2 g_CS[(size_t)TSEQ*(CDIM/2)];

// ------------------------------ ptx helpers --------------------------------
__device__ __forceinline__ uint32_t smem_u32(const void* p) {
    uint32_t a;
    asm("{ .reg .u64 t; cvta.to.shared.u64 t, %1; cvt.u32.u64 %0, t; }"
        : "=r"(a) : "l"(p));
    return a;
}
__device__ __forceinline__ void cp16(uint32_t dst, const void* src) {
    asm volatile("cp.async.cg.shared.global [%0], [%1], 16;" :: "r"(dst), "l"(src));
}
#define CP_COMMIT() asm volatile("cp.async.commit_group;")
#define CP_WAIT0()  asm volatile("cp.async.wait_group 0;")
#define CP_WAIT1()  asm volatile("cp.async.wait_group 1;")

__device__ __forceinline__ void ldm_x4(uint32_t* r, uint32_t addr) {
    asm volatile("ldmatrix.sync.aligned.m8n8.x4.shared.b16 {%0,%1,%2,%3}, [%4];"
                 : "=r"(r[0]), "=r"(r[1]), "=r"(r[2]), "=r"(r[3]) : "r"(addr));
}
__device__ __forceinline__ void ldm_x2(uint32_t* r, uint32_t addr) {
    asm volatile("ldmatrix.sync.aligned.m8n8.x2.shared.b16 {%0,%1}, [%2];"
                 : "=r"(r[0]), "=r"(r[1]) : "r"(addr));
}
__device__ __forceinline__ void mma16816(float* c, const uint32_t* a, const uint32_t* b) {
    asm volatile("mma.sync.aligned.m16n8k16.row.col.f32.bf16.bf16.f32 "
                 "{%0,%1,%2,%3}, {%4,%5,%6,%7}, {%8,%9}, {%0,%1,%2,%3};"
                 : "+f"(c[0]), "+f"(c[1]), "+f"(c[2]), "+f"(c[3])
                 : "r"(a[0]), "r"(a[1]), "r"(a[2]), "r"(a[3]), "r"(b[0]), "r"(b[1]));
}
__device__ __forceinline__ uint32_t pack_bf16(float x, float y) {
    __nv_bfloat162 h = __floats2bfloat162_rn(x, y);
    return *(uint32_t*)&h;
}

// ---------------------------------------------------------------------------
// HMMA split-bf16 NT GEMM:  C[m,n] = scale*sum_k A[m,k]*B[n,k] (+bias,+RoPE)
// 3 segments (hi*hi + hi*lo + lo*hi) into fp32 accumulators.
// CMODE: 0 none, 1 causal tile-skip, 2 causal k-limit.  OSPLIT: fp32 vs bf16 hi/lo out.
// ---------------------------------------------------------------------------
template<int ROPE, int CMODE, int OSPLIT>
__global__ void __launch_bounds__(256, 2) gemm_mma(
    const bf16* __restrict__ Ahi, const bf16* __restrict__ Alo,
    const bf16* __restrict__ Bhi, const bf16* __restrict__ Blo,
    const float* __restrict__ bias, const float2* __restrict__ cs,
    float* __restrict__ Cf, bf16* __restrict__ Chi, bf16* __restrict__ Clo,
    int N, int K, long sA, long sB, long sC, float scale)
{
    int m0 = blockIdx.y * 128, n0 = blockIdx.x * 128;
    if (CMODE == 1 && n0 > m0 + 127) return;
    long z = blockIdx.z;
    Ahi += z * sA; Alo += z * sA; Bhi += z * sB; Blo += z * sB;
    if (OSPLIT) { Chi += z * sC; Clo += z * sC; } else { Cf += z * sC; }

    __shared__ __align__(16) bf16 As[2][128 * LDP];
    __shared__ __align__(16) bf16 Bs[2][128 * LDP];

    int tid = threadIdx.x, lane = tid & 31, wid = tid >> 5;
    int wm = wid & 1, wn = wid >> 1;          // warp tile: rows wm*64, cols wn*32

    int kmax = (CMODE == 2) ? (m0 + 128) : K;
    int nch = kmax / KC;
    int tot = 3 * nch;

    int lrow = tid >> 2, lc8 = tid & 3;       // loader: rows lrow, lrow+64; 16B chunk lc8
    uint32_t a_s = smem_u32(As), b_s = smem_u32(Bs);
    uint32_t adst = a_s + (lrow * LDP + lc8 * 8) * 2;
    uint32_t bdst = b_s + (lrow * LDP + lc8 * 8) * 2;

    float acc[4][4][4];
    #pragma unroll
    for (int i = 0; i < 4; i++)
        #pragma unroll
        for (int j = 0; j < 4; j++)
            #pragma unroll
            for (int q = 0; q < 4; q++) acc[i][j][q] = 0.f;

    auto load = [&](int c) {
        int seg = c / nch, ch = c - seg * nch;
        int k0 = ch * KC;
        const bf16* A = (seg < 2) ? Ahi : Alo;
        const bf16* B = (seg == 1) ? Blo : Bhi;
        const bf16* sa = A + (size_t)(m0 + lrow) * K + k0 + lc8 * 8;
        const bf16* sb = B + (size_t)(n0 + lrow) * K + k0 + lc8 * 8;
        uint32_t off = (c & 1) ? (uint32_t)TILE_BYTES : 0u;
        cp16(adst + off, sa);
        cp16(adst + off + 64 * LDP * 2, sa + (size_t)64 * K);
        cp16(bdst + off, sb);
        cp16(bdst + off + 64 * LDP * 2, sb + (size_t)64 * K);
        CP_COMMIT();
    };

    load(0);
    for (int c = 0; c < tot; c++) {
        if (c + 1 < tot) { load(c + 1); CP_WAIT1(); }
        else             { CP_WAIT0(); }
        __syncthreads();

        uint32_t ab = a_s + (c & 1) * TILE_BYTES;
        uint32_t bb = b_s + (c & 1) * TILE_BYTES;
        #pragma unroll
        for (int kk = 0; kk < 2; kk++) {
            uint32_t afr[4][4], bfr[4][2];
            int ar = (lane & 7) + ((lane >> 3) & 1) * 8;
            int ak = kk * 16 + (lane >> 4) * 8;
            #pragma unroll
            for (int mi = 0; mi < 4; mi++)
                ldm_x4(afr[mi], ab + ((wm * 64 + mi * 16 + ar) * LDP + ak) * 2);
            int l4 = lane & 15;
            int br = l4 & 7;
            int bk = kk * 16 + ((l4 >> 3) & 1) * 8;
            #pragma unroll
            for (int ni = 0; ni < 4; ni++)
                ldm_x2(bfr[ni], bb + ((wn * 32 + ni * 8 + br) * LDP + bk) * 2);
            #pragma unroll
            for (int mi = 0; mi < 4; mi++)
                #pragma unroll
                for (int ni = 0; ni < 4; ni++)
                    mma16816(acc[mi][ni], afr[mi], bfr[ni]);
        }
        __syncthreads();
    }

    // epilogue: fragment c0,c1 -> row g, cols qc,qc+1 ; c2,c3 -> row g+8
    int gr = lane >> 2, qc = (lane & 3) * 2;
    #pragma unroll
    for (int mi = 0; mi < 4; mi++) {
        #pragma unroll
        for (int half = 0; half < 2; half++) {
            int m = m0 + wm * 64 + mi * 16 + gr + half * 8;
            int t = m & (TSEQ - 1);
            #pragma unroll
            for (int ni = 0; ni < 4; ni++) {
                int n = n0 + wn * 32 + ni * 8 + qc;
                float v0 = acc[mi][ni][half * 2 + 0] * scale;
                float v1 = acc[mi][ni][half * 2 + 1] * scale;
                if (bias) { v0 += bias[n]; v1 += bias[n + 1]; }
                if (ROPE) {
                    float2 sc = cs[(size_t)t * (CDIM / 2) + (n >> 1)];
                    float a = v0, b = v1;
                    v0 = a * sc.x - b * sc.y;
                    v1 = b * sc.x + a * sc.y;
                }
                if (OSPLIT) {
                    float h0f = __bfloat162float(__float2bfloat16_rn(v0));
                    float h1f = __bfloat162float(__float2bfloat16_rn(v1));
                    *(uint32_t*)&Chi[(size_t)m * N + n] = pack_bf16(h0f, h1f);
                    *(uint32_t*)&Clo[(size_t)m * N + n] = pack_bf16(v0 - h0f, v1 - h1f);
                } else {
                    *(float2*)&Cf[(size_t)m * N + n] = make_float2(v0, v1);
                }
            }
        }
    }
}

// ---------------------------------------------------------------------------
// aux kernels
// ---------------------------------------------------------------------------
__global__ void __launch_bounds__(256) rope_table_k(float2* __restrict__ cs)
{
    int idx = blockIdx.x * 256 + threadIdx.x;
    int t = idx / (CDIM / 2);
    int p = idx % (CDIM / 2);
    float freq = powf(10000.0f, -(float)(2 * p) / (float)CDIM);
    float ang = (float)t * freq;
    float s, c;
    sincosf(ang, &s, &c);
    cs[idx] = make_float2(c, s);
}

__global__ void __launch_bounds__(256) split2_k(
    const float4* __restrict__ in, bf16* __restrict__ hi, bf16* __restrict__ lo, int n4)
{
    int i = blockIdx.x * 256 + threadIdx.x;
    if (i >= n4) return;
    float4 v = in[i];
    float f[4] = {v.x, v.y, v.z, v.w};
    bf16 h[4], l[4];
    #pragma unroll
    for (int c = 0; c < 4; c++) {
        h[c] = __float2bfloat16_rn(f[c]);
        l[c] = __float2bfloat16_rn(f[c] - __bfloat162float(h[c]));
    }
    *(uint2*)&hi[(size_t)i * 4] = *(uint2*)h;
    *(uint2*)&lo[(size_t)i * 4] = *(uint2*)l;
}

// transpose+split V: [B,T,C] fp32 -> [B,C,T] bf16 hi/lo
__global__ void __launch_bounds__(256) tsplit_v_k(
    const float* __restrict__ V, bf16* __restrict__ Th, bf16* __restrict__ Tl)
{
    __shared__ float tile[32][33];
    int t0 = blockIdx.x * 32, c0 = blockIdx.y * 32, z = blockIdx.z;
    int tx = threadIdx.x, ty = threadIdx.y;   // 32 x 8
    const float* Vz = V + (size_t)z * TSEQ * CDIM;
    #pragma unroll
    for (int i = 0; i < 4; i++)
        tile[ty + 8 * i][tx] = Vz[(size_t)(t0 + ty + 8 * i) * CDIM + c0 + tx];
    __syncthreads();
    size_t ob = (size_t)z * CDIM * TSEQ;
    #pragma unroll
    for (int i = 0; i < 4; i++) {
        float v = tile[tx][ty + 8 * i];
        bf16 h = __float2bfloat16_rn(v);
        size_t o = ob + (size_t)(c0 + ty + 8 * i) * TSEQ + t0 + tx;
        Th[o] = h;
        Tl[o] = __float2bfloat16_rn(v - __bfloat162float(h));
    }
}

// causal softmax on S; writes split bf16 probabilities Phi/Plo (full rows,
// masked lanes = 0) so the PV GEMM needs no extra split pass.
__global__ void __launch_bounds__(256) softmax_split_k(
    const float* __restrict__ S, bf16* __restrict__ Phi, bf16* __restrict__ Plo)
{
    long row = blockIdx.x;
    long b = row >> 11;
    int  t = (int)(row & (TSEQ - 1));
    const float* p = S + (b << 22) + ((long)t << 11);
    bf16* ph = Phi + (b << 22) + ((long)t << 11);
    bf16* pl = Plo + (b << 22) + ((long)t << 11);
    int n = t + 1;
    int tid = threadIdx.x;

    float4 v[2];
    float mx = -INFINITY;
    #pragma unroll
    for (int i = 0; i < 2; i++) {
        int q = tid + 256 * i;
        v[i] = *(const float4*)(p + q * 4);
        float* f = (float*)&v[i];
        int base = q * 4;
        #pragma unroll
        for (int c = 0; c < 4; c++) {
            if (base + c >= n) f[c] = -INFINITY;
            mx = fmaxf(mx, f[c]);
        }
    }
    __shared__ float red[8];
    #pragma unroll
    for (int o = 16; o; o >>= 1) mx = fmaxf(mx, __shfl_xor_sync(~0u, mx, o));
    if ((tid & 31) == 0) red[tid >> 5] = mx;
    __syncthreads();
    mx = red[0];
    #pragma unroll
    for (int k = 1; k < 8; k++) mx = fmaxf(mx, red[k]);
    __syncthreads();

    float sum = 0.f;
    #pragma unroll
    for (int i = 0; i < 2; i++) {
        float* f = (float*)&v[i];
        #pragma unroll
        for (int c = 0; c < 4; c++) {
            float e = expf(f[c] - mx);
            f[c] = e;
            sum += e;
        }
    }
    #pragma unroll
    for (int o = 16; o; o >>= 1) sum += __shfl_xor_sync(~0u, sum, o);
    if ((tid & 31) == 0) red[tid >> 5] = sum;
    __syncthreads();
    sum = 0.f;
    #pragma unroll
    for (int k = 0; k < 8; k++) sum += red[k];
    float inv = 1.0f / sum;

    #pragma unroll
    for (int i = 0; i < 2; i++) {
        int q = tid + 256 * i;
        float* f = (float*)&v[i];
        bf16 h[4], l[4];
        #pragma unroll
        for (int c = 0; c < 4; c++) {
            float pv = f[c] * inv;
            h[c] = __float2bfloat16_rn(pv);
            l[c] = __float2bfloat16_rn(pv - __bfloat162float(h[c]));
        }
        *(uint2*)(ph + q * 4) = *(uint2*)h;
        *(uint2*)(pl + q * 4) = *(uint2*)l;
    }
}

// ---------------------------------------------------------------------------
extern "C" void kernel_launch(void* const* d_in, const int* in_sizes, int n_in,
                              void* d_out, int out_size)
{
    const float* x  = (const float*)d_in[0];
    const float* Wq = (const float*)d_in[1];
    const float* bq = (const float*)d_in[2];
    const float* Wk = (const float*)d_in[3];
    const float* bk = (const float*)d_in[4];
    const float* Wv = (const float*)d_in[5];
    const float* bv = (const float*)d_in[6];
    const float* Wf = (const float*)d_in[7];
    const float* bf = (const float*)d_in[8];
    float* out = (float*)d_out;

    bf16 *Xhi,*Xlo,*Wqh,*Wql,*Wkh,*Wkl,*Wvh,*Wvl,*Wfh,*Wfl;
    bf16 *Qhi,*Qlo,*Khi,*Klo,*Vth,*Vtl,*Phi,*Plo,*Ohi,*Olo;
    float *V,*S;
    float2* CS;
    cudaGetSymbolAddress((void**)&Xhi, g_Xhi); cudaGetSymbolAddress((void**)&Xlo, g_Xlo);
    cudaGetSymbolAddress((void**)&Wqh, g_Wqh); cudaGetSymbolAddress((void**)&Wql, g_Wql);
    cudaGetSymbolAddress((void**)&Wkh, g_Wkh); cudaGetSymbolAddress((void**)&Wkl, g_Wkl);
    cudaGetSymbolAddress((void**)&Wvh, g_Wvh); cudaGetSymbolAddress((void**)&Wvl, g_Wvl);
    cudaGetSymbolAddress((void**)&Wfh, g_Wfh); cudaGetSymbolAddress((void**)&Wfl, g_Wfl);
    cudaGetSymbolAddress((void**)&Qhi, g_Qhi); cudaGetSymbolAddress((void**)&Qlo, g_Qlo);
    cudaGetSymbolAddress((void**)&Khi, g_Khi); cudaGetSymbolAddress((void**)&Klo, g_Klo);
    cudaGetSymbolAddress((void**)&V,   g_V);
    cudaGetSymbolAddress((void**)&Vth, g_Vth); cudaGetSymbolAddress((void**)&Vtl, g_Vtl);
    cudaGetSymbolAddress((void**)&S,   g_S);
    cudaGetSymbolAddress((void**)&Phi, g_Phi); cudaGetSymbolAddress((void**)&Plo, g_Plo);
    cudaGetSymbolAddress((void**)&Ohi, g_Ohi); cudaGetSymbolAddress((void**)&Olo, g_Olo);
    cudaGetSymbolAddress((void**)&CS,  g_CS);

    dim3 blk(256);

    rope_table_k<<<TSEQ * (CDIM / 2) / 256, blk>>>(CS);

    split2_k<<<(MTOT * CDIM / 4 + 255) / 256, blk>>>((const float4*)x, Xhi, Xlo, MTOT * CDIM / 4);
    split2_k<<<(CDIM * CDIM / 4 + 255) / 256, blk>>>((const float4*)Wq, Wqh, Wql, CDIM * CDIM / 4);
    split2_k<<<(CDIM * CDIM / 4 + 255) / 256, blk>>>((const float4*)Wk, Wkh, Wkl, CDIM * CDIM / 4);
    split2_k<<<(CDIM * CDIM / 4 + 255) / 256, blk>>>((const float4*)Wv, Wvh, Wvl, CDIM * CDIM / 4);
    split2_k<<<(CDIM * CDIM / 4 + 255) / 256, blk>>>((const float4*)Wf, Wfh, Wfl, CDIM * CDIM / 4);

    dim3 gProj(CDIM / 128, MTOT / 128, 1);   // 8 x 64

    // Q = rope(x Wq^T + bq) -> split bf16
    gemm_mma<1,0,1><<<gProj, blk>>>(Xhi, Xlo, Wqh, Wql, bq, CS,
                                    nullptr, Qhi, Qlo, CDIM, CDIM, 0, 0, 0, 1.0f);
    gemm_mma<1,0,1><<<gProj, blk>>>(Xhi, Xlo, Wkh, Wkl, bk, CS,
                                    nullptr, Khi, Klo, CDIM, CDIM, 0, 0, 0, 1.0f);
    // V fp32
    gemm_mma<0,0,0><<<gProj, blk>>>(Xhi, Xlo, Wvh, Wvl, bv, nullptr,
                                    V, nullptr, nullptr, CDIM, CDIM, 0, 0, 0, 1.0f);
    // V^T split
    dim3 gT(TSEQ / 32, CDIM / 32, BSZ);
    tsplit_v_k<<<gT, dim3(32, 8)>>>(V, Vth, Vtl);

    // S = Q K^T / 32 (causal tile-skip)
    dim3 gS(TSEQ / 128, TSEQ / 128, BSZ);    // 16 x 16 x 4
    gemm_mma<0,1,0><<<gS, blk>>>(Qhi, Qlo, Khi, Klo, nullptr, nullptr,
                                 S, nullptr, nullptr, TSEQ, CDIM,
                                 (long)TSEQ * CDIM, (long)TSEQ * CDIM,
                                 (long)TSEQ * TSEQ, 1.0f / 32.0f);

    // softmax + P split (fused)
    softmax_split_k<<<BSZ * TSEQ, blk>>>(S, Phi, Plo);

    // O = P V (causal k-limit) -> split bf16
    dim3 gPV(CDIM / 128, TSEQ / 128, BSZ);   // 8 x 16 x 4
    gemm_mma<0,2,1><<<gPV, blk>>>(Phi, Plo, Vth, Vtl, nullptr, nullptr,
                                  nullptr, Ohi, Olo, CDIM, TSEQ,
                                  (long)TSEQ * TSEQ, (long)CDIM * TSEQ,
                                  (long)TSEQ * CDIM, 1.0f);

    // out = O Wf^T + bf
    gemm_mma<0,0,0><<<gProj, blk>>>(Ohi, Olo, Wfh, Wfl, bf, nullptr,
                                    out, nullptr, nullptr, CDIM, CDIM, 0, 0, 0, 1.0f);
}

// round 6
// speedup vs baseline: 8.7093x; 2.8324x over previous
#include <cuda_runtime.h>
#include <cuda_fp16.h>
#include <math.h>
#include <cstdint>

#define BSZ  4
#define TSEQ 2048
#define CDIM 1024
#define MTOT (BSZ*TSEQ)

#define KC 32
#define LDP 40                       // padded row length (halfs) for smem tiles
#define TILE_BYTES (128*LDP*2)

// ------------------------- persistent scratch ------------------------------
__device__ __align__(16) __half g_X16[(size_t)MTOT*CDIM];
__device__ __align__(16) __half g_Wq16[(size_t)CDIM*CDIM];
__device__ __align__(16) __half g_Wk16[(size_t)CDIM*CDIM];
__device__ __align__(16) __half g_Wv16[(size_t)CDIM*CDIM];
__device__ __align__(16) __half g_Wf16[(size_t)CDIM*CDIM];
__device__ __align__(16) __half g_Q16[(size_t)MTOT*CDIM];
__device__ __align__(16) __half g_K16[(size_t)MTOT*CDIM];
__device__ __align__(16) float  g_V  [(size_t)MTOT*CDIM];
__device__ __align__(16) __half g_Vt [(size_t)BSZ*CDIM*TSEQ];
__device__ __align__(16) float  g_S  [(size_t)BSZ*TSEQ*TSEQ];
__device__ __align__(16) __half g_P  [(size_t)BSZ*TSEQ*TSEQ];
__device__ __align__(16) __half g_O16[(size_t)MTOT*CDIM];
__device__ __align__(16) float2 g_CS [(size_t)TSEQ*(CDIM/2)];

// ------------------------------ ptx helpers --------------------------------
__device__ __forceinline__ uint32_t smem_u32(const void* p) {
    uint32_t a;
    asm("{ .reg .u64 t; cvta.to.shared.u64 t, %1; cvt.u32.u64 %0, t; }"
        : "=r"(a) : "l"(p));
    return a;
}
__device__ __forceinline__ void cp16(uint32_t dst, const void* src) {
    asm volatile("cp.async.cg.shared.global [%0], [%1], 16;" :: "r"(dst), "l"(src));
}
#define CP_COMMIT() asm volatile("cp.async.commit_group;")
#define CP_WAIT0()  asm volatile("cp.async.wait_group 0;")
#define CP_WAIT1()  asm volatile("cp.async.wait_group 1;")

__device__ __forceinline__ void ldm_x4(uint32_t* r, uint32_t addr) {
    asm volatile("ldmatrix.sync.aligned.m8n8.x4.shared.b16 {%0,%1,%2,%3}, [%4];"
                 : "=r"(r[0]), "=r"(r[1]), "=r"(r[2]), "=r"(r[3]) : "r"(addr));
}
__device__ __forceinline__ void mma16816h(float* c, const uint32_t* a, const uint32_t* b) {
    asm volatile("mma.sync.aligned.m16n8k16.row.col.f32.f16.f16.f32 "
                 "{%0,%1,%2,%3}, {%4,%5,%6,%7}, {%8,%9}, {%0,%1,%2,%3};"
                 : "+f"(c[0]), "+f"(c[1]), "+f"(c[2]), "+f"(c[3])
                 : "r"(a[0]), "r"(a[1]), "r"(a[2]), "r"(a[3]), "r"(b[0]), "r"(b[1]));
}
__device__ __forceinline__ uint32_t pack_h2(float x, float y) {
    __half2 h = __floats2half2_rn(x, y);
    return *(uint32_t*)&h;
}

// ---------------------------------------------------------------------------
// fp16 single-pass NT GEMM:  C[m,n] = scale*sum_k A[m,k]*B[n,k] (+bias,+RoPE)
// A: M x K row-major fp16, B: N x K row-major fp16, fp32 accumulate.
// CMODE: 0 none, 1 causal tile-skip, 2 causal k-limit.
// OUT16: 1 -> Ch fp16, 0 -> Cf fp32.
// ---------------------------------------------------------------------------
template<int ROPE, int CMODE, int OUT16>
__global__ void __launch_bounds__(256, 2) gemm_h(
    const __half* __restrict__ A, const __half* __restrict__ B,
    const float* __restrict__ bias, const float2* __restrict__ cs,
    float* __restrict__ Cf, __half* __restrict__ Ch,
    int N, int K, long sA, long sB, long sC, float scale)
{
    int m0 = blockIdx.y * 128, n0 = blockIdx.x * 128;
    if (CMODE == 1 && n0 > m0 + 127) return;
    long z = blockIdx.z;
    A += z * sA; B += z * sB;
    if (OUT16) Ch += z * sC; else Cf += z * sC;

    __shared__ __align__(16) __half As[2][128 * LDP];
    __shared__ __align__(16) __half Bs[2][128 * LDP];

    int tid = threadIdx.x, lane = tid & 31, wid = tid >> 5;
    int wm = wid & 1, wn = wid >> 1;          // warp tile: rows wm*64, cols wn*32

    int kmax = (CMODE == 2) ? (m0 + 128) : K;
    int tot = kmax / KC;

    int lrow = tid >> 2, lc8 = tid & 3;       // loader rows lrow, lrow+64; 16B chunk
    uint32_t a_s = smem_u32(As), b_s = smem_u32(Bs);
    uint32_t adst = a_s + (lrow * LDP + lc8 * 8) * 2;
    uint32_t bdst = b_s + (lrow * LDP + lc8 * 8) * 2;

    float acc[4][4][4];
    #pragma unroll
    for (int i = 0; i < 4; i++)
        #pragma unroll
        for (int j = 0; j < 4; j++)
            #pragma unroll
            for (int q = 0; q < 4; q++) acc[i][j][q] = 0.f;

    auto load = [&](int c) {
        int k0 = c * KC;
        const __half* sa = A + (size_t)(m0 + lrow) * K + k0 + lc8 * 8;
        const __half* sb = B + (size_t)(n0 + lrow) * K + k0 + lc8 * 8;
        uint32_t off = (c & 1) ? (uint32_t)TILE_BYTES : 0u;
        cp16(adst + off, sa);
        cp16(adst + off + 64 * LDP * 2, sa + (size_t)64 * K);
        cp16(bdst + off, sb);
        cp16(bdst + off + 64 * LDP * 2, sb + (size_t)64 * K);
        CP_COMMIT();
    };

    load(0);
    for (int c = 0; c < tot; c++) {
        if (c + 1 < tot) { load(c + 1); CP_WAIT1(); }
        else             { CP_WAIT0(); }
        __syncthreads();

        uint32_t ab = a_s + (c & 1) * TILE_BYTES;
        uint32_t bb = b_s + (c & 1) * TILE_BYTES;
        #pragma unroll
        for (int kk = 0; kk < 2; kk++) {
            uint32_t afr[4][4], bfr[2][4];
            // A: matrices [m0-7@k0, m8-15@k0, m0-7@k8, m8-15@k8]
            int ar = (lane & 7) + ((lane >> 3) & 1) * 8;
            int ak = kk * 16 + (lane >> 4) * 8;
            #pragma unroll
            for (int mi = 0; mi < 4; mi++)
                ldm_x4(afr[mi], ab + ((wm * 64 + mi * 16 + ar) * LDP + ak) * 2);
            // B merged x4: matrices [n(2p)@k0, n(2p)@k8, n(2p+1)@k0, n(2p+1)@k8]
            int brow = (lane & 7) + ((lane >> 4) & 1) * 8;
            int bcol = kk * 16 + ((lane >> 3) & 1) * 8;
            #pragma unroll
            for (int p = 0; p < 2; p++)
                ldm_x4(bfr[p], bb + ((wn * 32 + p * 16 + brow) * LDP + bcol) * 2);
            #pragma unroll
            for (int mi = 0; mi < 4; mi++)
                #pragma unroll
                for (int ni = 0; ni < 4; ni++)
                    mma16816h(acc[mi][ni], afr[mi], &bfr[ni >> 1][(ni & 1) * 2]);
        }
        __syncthreads();
    }

    // epilogue
    int gr = lane >> 2, qc = (lane & 3) * 2;
    #pragma unroll
    for (int mi = 0; mi < 4; mi++) {
        #pragma unroll
        for (int half_ = 0; half_ < 2; half_++) {
            int m = m0 + wm * 64 + mi * 16 + gr + half_ * 8;
            int t = m & (TSEQ - 1);
            #pragma unroll
            for (int ni = 0; ni < 4; ni++) {
                int n = n0 + wn * 32 + ni * 8 + qc;
                float v0 = acc[mi][ni][half_ * 2 + 0] * scale;
                float v1 = acc[mi][ni][half_ * 2 + 1] * scale;
                if (bias) { v0 += bias[n]; v1 += bias[n + 1]; }
                if (ROPE) {
                    float2 sc = cs[(size_t)t * (CDIM / 2) + (n >> 1)];
                    float a = v0, b = v1;
                    v0 = a * sc.x - b * sc.y;
                    v1 = b * sc.x + a * sc.y;
                }
                if (OUT16) {
                    *(uint32_t*)&Ch[(size_t)m * N + n] = pack_h2(v0, v1);
                } else {
                    *(float2*)&Cf[(size_t)m * N + n] = make_float2(v0, v1);
                }
            }
        }
    }
}

// ---------------------------------------------------------------------------
// aux kernels
// ---------------------------------------------------------------------------
__global__ void __launch_bounds__(256) rope_table_k(float2* __restrict__ cs)
{
    int idx = blockIdx.x * 256 + threadIdx.x;
    int t = idx / (CDIM / 2);
    int p = idx % (CDIM / 2);
    float freq = powf(10000.0f, -(float)(2 * p) / (float)CDIM);
    float ang = (float)t * freq;
    float s, c;
    sincosf(ang, &s, &c);
    cs[idx] = make_float2(c, s);
}

__global__ void __launch_bounds__(256) cvt_h_k(
    const float4* __restrict__ in, __half* __restrict__ out, int n4)
{
    int i = blockIdx.x * 256 + threadIdx.x;
    if (i >= n4) return;
    float4 v = in[i];
    uint32_t lo = pack_h2(v.x, v.y), hi = pack_h2(v.z, v.w);
    *(uint2*)&out[(size_t)i * 4] = make_uint2(lo, hi);
}

// transpose V: [B,T,C] fp32 -> [B,C,T] fp16
__global__ void __launch_bounds__(256) tcvt_v_k(
    const float* __restrict__ V, __half* __restrict__ Vt)
{
    __shared__ float tile[32][33];
    int t0 = blockIdx.x * 32, c0 = blockIdx.y * 32, z = blockIdx.z;
    int tx = threadIdx.x, ty = threadIdx.y;   // 32 x 8
    const float* Vz = V + (size_t)z * TSEQ * CDIM;
    #pragma unroll
    for (int i = 0; i < 4; i++)
        tile[ty + 8 * i][tx] = Vz[(size_t)(t0 + ty + 8 * i) * CDIM + c0 + tx];
    __syncthreads();
    size_t ob = (size_t)z * CDIM * TSEQ;
    #pragma unroll
    for (int i = 0; i < 4; i++)
        Vt[ob + (size_t)(c0 + ty + 8 * i) * TSEQ + t0 + tx] =
            __float2half_rn(tile[tx][ty + 8 * i]);
}

// causal softmax: reads fp32 scores (prefix only), writes fp16 probabilities,
// zero-padded through the end of the row's 128-block (for the PV k-limit).
__global__ void __launch_bounds__(256) softmax_h_k(
    const float* __restrict__ S, __half* __restrict__ P)
{
    long row = blockIdx.x;
    long b = row >> 11;
    int  t = (int)(row & (TSEQ - 1));
    const float* p = S + (b << 22) + ((long)t << 11);
    __half* ph = P + (b << 22) + ((long)t << 11);
    int n = t + 1;
    int kend = ((t >> 7) + 1) << 7;
    int tid = threadIdx.x;

    float4 v[2];
    float mx = -INFINITY;
    #pragma unroll
    for (int i = 0; i < 2; i++) {
        int base = (tid + 256 * i) * 4;
        if (base < n) {
            v[i] = *(const float4*)(p + base);
            float* f = (float*)&v[i];
            #pragma unroll
            for (int c = 0; c < 4; c++) {
                if (base + c >= n) f[c] = -INFINITY;
                mx = fmaxf(mx, f[c]);
            }
        } else {
            v[i] = make_float4(-INFINITY, -INFINITY, -INFINITY, -INFINITY);
        }
    }
    __shared__ float red[8];
    #pragma unroll
    for (int o = 16; o; o >>= 1) mx = fmaxf(mx, __shfl_xor_sync(~0u, mx, o));
    if ((tid & 31) == 0) red[tid >> 5] = mx;
    __syncthreads();
    mx = red[0];
    #pragma unroll
    for (int k = 1; k < 8; k++) mx = fmaxf(mx, red[k]);
    __syncthreads();

    float sum = 0.f;
    #pragma unroll
    for (int i = 0; i < 2; i++) {
        float* f = (float*)&v[i];
        #pragma unroll
        for (int c = 0; c < 4; c++) {
            float e = expf(f[c] - mx);   // exp(-inf)=0
            f[c] = e;
            sum += e;
        }
    }
    #pragma unroll
    for (int o = 16; o; o >>= 1) sum += __shfl_xor_sync(~0u, sum, o);
    if ((tid & 31) == 0) red[tid >> 5] = sum;
    __syncthreads();
    sum = 0.f;
    #pragma unroll
    for (int k = 0; k < 8; k++) sum += red[k];
    float inv = 1.0f / sum;

    #pragma unroll
    for (int i = 0; i < 2; i++) {
        int base = (tid + 256 * i) * 4;
        if (base < kend) {
            float* f = (float*)&v[i];
            uint32_t lo = pack_h2(f[0] * inv, f[1] * inv);
            uint32_t hi = pack_h2(f[2] * inv, f[3] * inv);
            *(uint2*)(ph + base) = make_uint2(lo, hi);
        }
    }
}

// ---------------------------------------------------------------------------
extern "C" void kernel_launch(void* const* d_in, const int* in_sizes, int n_in,
                              void* d_out, int out_size)
{
    const float* x  = (const float*)d_in[0];
    const float* Wq = (const float*)d_in[1];
    const float* bq = (const float*)d_in[2];
    const float* Wk = (const float*)d_in[3];
    const float* bk = (const float*)d_in[4];
    const float* Wv = (const float*)d_in[5];
    const float* bv = (const float*)d_in[6];
    const float* Wf = (const float*)d_in[7];
    const float* bf = (const float*)d_in[8];
    float* out = (float*)d_out;

    __half *X16,*Wq16,*Wk16,*Wv16,*Wf16,*Q16,*K16,*Vt,*P,*O16;
    float *V,*S;
    float2* CS;
    cudaGetSymbolAddress((void**)&X16,  g_X16);
    cudaGetSymbolAddress((void**)&Wq16, g_Wq16);
    cudaGetSymbolAddress((void**)&Wk16, g_Wk16);
    cudaGetSymbolAddress((void**)&Wv16, g_Wv16);
    cudaGetSymbolAddress((void**)&Wf16, g_Wf16);
    cudaGetSymbolAddress((void**)&Q16,  g_Q16);
    cudaGetSymbolAddress((void**)&K16,  g_K16);
    cudaGetSymbolAddress((void**)&V,    g_V);
    cudaGetSymbolAddress((void**)&Vt,   g_Vt);
    cudaGetSymbolAddress((void**)&S,    g_S);
    cudaGetSymbolAddress((void**)&P,    g_P);
    cudaGetSymbolAddress((void**)&O16,  g_O16);
    cudaGetSymbolAddress((void**)&CS,   g_CS);

    dim3 blk(256);

    rope_table_k<<<TSEQ * (CDIM / 2) / 256, blk>>>(CS);

    cvt_h_k<<<MTOT * CDIM / 4 / 256, blk>>>((const float4*)x, X16, MTOT * CDIM / 4);
    cvt_h_k<<<CDIM * CDIM / 4 / 256, blk>>>((const float4*)Wq, Wq16, CDIM * CDIM / 4);
    cvt_h_k<<<CDIM * CDIM / 4 / 256, blk>>>((const float4*)Wk, Wk16, CDIM * CDIM / 4);
    cvt_h_k<<<CDIM * CDIM / 4 / 256, blk>>>((const float4*)Wv, Wv16, CDIM * CDIM / 4);
    cvt_h_k<<<CDIM * CDIM / 4 / 256, blk>>>((const float4*)Wf, Wf16, CDIM * CDIM / 4);

    dim3 gProj(CDIM / 128, MTOT / 128, 1);   // 8 x 64

    // Q = rope(x Wq^T + bq) -> fp16 ; K likewise
    gemm_h<1,0,1><<<gProj, blk>>>(X16, Wq16, bq, CS, nullptr, Q16,
                                  CDIM, CDIM, 0, 0, 0, 1.0f);
    gemm_h<1,0,1><<<gProj, blk>>>(X16, Wk16, bk, CS, nullptr, K16,
                                  CDIM, CDIM, 0, 0, 0, 1.0f);
    // V (fp32 out, for accurate transpose+convert)
    gemm_h<0,0,0><<<gProj, blk>>>(X16, Wv16, bv, nullptr, V, nullptr,
                                  CDIM, CDIM, 0, 0, 0, 1.0f);
    dim3 gT(TSEQ / 32, CDIM / 32, BSZ);
    tcvt_v_k<<<gT, dim3(32, 8)>>>(V, Vt);

    // S = Q K^T / 32 (causal tile-skip), fp32 scores
    dim3 gS(TSEQ / 128, TSEQ / 128, BSZ);    // 16 x 16 x 4
    gemm_h<0,1,0><<<gS, blk>>>(Q16, K16, nullptr, nullptr, S, nullptr,
                               TSEQ, CDIM,
                               (long)TSEQ * CDIM, (long)TSEQ * CDIM,
                               (long)TSEQ * TSEQ, 1.0f / 32.0f);

    softmax_h_k<<<BSZ * TSEQ, blk>>>(S, P);

    // O = P V (causal k-limit) -> fp16
    dim3 gPV(CDIM / 128, TSEQ / 128, BSZ);   // 8 x 16 x 4
    gemm_h<0,2,1><<<gPV, blk>>>(P, Vt, nullptr, nullptr, nullptr, O16,
                                CDIM, TSEQ,
                                (long)TSEQ * TSEQ, (long)CDIM * TSEQ,
                                (long)TSEQ * CDIM, 1.0f);

    // out = O Wf^T + bf (fp32 out)
    gemm_h<0,0,0><<<gProj, blk>>>(O16, Wf16, bf, nullptr, out, nullptr,
                                  CDIM, CDIM, 0, 0, 0, 1.0f);
}